// round 2
// baseline (speedup 1.0000x reference)
#include <cuda_runtime.h>

// Problem constants (fixed by the reference)
#define E    1024
#define NBLK 6
#define FF   4096
#define NWA  8
#define NWF  4
#define CC   1000
#define BB   4096
#define TPB  1024

// ---------------- device scratch (no allocations allowed) ----------------
__device__ float g_attn[E];
__device__ float g_f[E];
__device__ float g_row[CC];
__device__ unsigned g_bar_count;
__device__ unsigned g_bar_gen;

// ---------------- software grid barrier (all CTAs resident) --------------
__device__ __forceinline__ void grid_sync() {
    __syncthreads();
    if (threadIdx.x == 0) {
        __threadfence();                                    // release our writes
        unsigned my = *((volatile unsigned*)&g_bar_gen);    // read gen BEFORE arriving
        unsigned old = atomicAdd(&g_bar_count, 1u);
        if (old == gridDim.x - 1) {
            *((volatile unsigned*)&g_bar_count) = 0u;
            __threadfence();
            atomicAdd(&g_bar_gen, 1u);
        } else {
            while (*((volatile unsigned*)&g_bar_gen) == my) { __nanosleep(64); }
        }
        __threadfence();                                    // acquire
    }
    __syncthreads();
}

// warp-per-output GEMV dot helper: row (global, float4-aligned), x in smem
template<int N4>  // number of float4 per row (E/4 or FF/4)
__device__ __forceinline__ float warp_dot(const float4* __restrict__ row,
                                          const float4* __restrict__ xs, int lane) {
    float acc = 0.f;
#pragma unroll 8
    for (int k = 0; k < N4 / 32; k++) {
        float4 w4 = row[lane + 32 * k];
        float4 x4 = xs[lane + 32 * k];
        acc = fmaf(w4.x, x4.x, acc);
        acc = fmaf(w4.y, x4.y, acc);
        acc = fmaf(w4.z, x4.z, acc);
        acc = fmaf(w4.w, x4.w, acc);
    }
#pragma unroll
    for (int o = 16; o; o >>= 1) acc += __shfl_xor_sync(0xffffffffu, acc, o);
    return acc;
}

extern "C" __global__ void __launch_bounds__(TPB, 1)
hkt_kernel(const float* __restrict__ Wv,
           const float* __restrict__ Wo,
           const float* __restrict__ phi_q,
           const float* __restrict__ W1,
           const float* __restrict__ W2,
           const float* __restrict__ phi_f,
           const float* __restrict__ ln1_g, const float* __restrict__ ln1_b,
           const float* __restrict__ ln2_g, const float* __restrict__ ln2_b,
           const float* __restrict__ Wc,   const float* __restrict__ bc,
           float* __restrict__ out)
{
    __shared__ __align__(16) float h_s[E];
    __shared__ __align__(16) float v_s[E];
    __shared__ __align__(16) float r_s[FF];
    __shared__ float red1_s[32];
    __shared__ float red2_s[32];
    __shared__ float m_s[NWA];
    __shared__ float stats[2];

    const int tid  = threadIdx.x;
    const int lane = tid & 31;
    const int wc   = tid >> 5;          // warp index in CTA (0..31)
    const int b    = blockIdx.x;
    const int nb   = gridDim.x;
    const int wstride = 32 * nb;        // total warps in grid

    // h0 = 1 + pe0 = [1,2,1,2,...]  (kern == 1 exactly; x is dead)
    h_s[tid] = 1.0f + (float)(tid & 1);
    __syncthreads();

    for (int blk = 0; blk < NBLK; blk++) {
        // ---- proj = cos(h[:8] + phi_q[blk]);  v = Wv[blk] @ proj (redundant per CTA) ----
        if (tid < NWA) m_s[tid] = cosf(h_s[tid] + phi_q[blk * NWA + tid]);
        __syncthreads();
        {
            const float4* wv = (const float4*)(Wv + (size_t)blk * E * NWA + (size_t)tid * NWA);
            float4 a = wv[0], c = wv[1];
            float acc = a.x * m_s[0] + a.y * m_s[1] + a.z * m_s[2] + a.w * m_s[3]
                      + c.x * m_s[4] + c.y * m_s[5] + c.z * m_s[6] + c.w * m_s[7];
            v_s[tid] = acc;
        }
        __syncthreads();

        // ---- attn[e] = dot(Wo[blk][e,:], v) : warp per output, grid-striped ----
        {
            const float4* vv = (const float4*)v_s;
            for (int e = wc * nb + b; e < E; e += wstride) {
                const float4* row = (const float4*)(Wo + (size_t)blk * E * E + (size_t)e * E);
                float acc = warp_dot<E / 4>(row, vv, lane);
                if (lane == 0) g_attn[e] = acc;
            }
        }
        grid_sync();

        // ---- h = LN1(h + attn)  (redundant, identical in every CTA) ----
        {
            float val = h_s[tid] + __ldcg(&g_attn[tid]);
            float s1 = val, s2 = val * val;
#pragma unroll
            for (int o = 16; o; o >>= 1) {
                s1 += __shfl_xor_sync(0xffffffffu, s1, o);
                s2 += __shfl_xor_sync(0xffffffffu, s2, o);
            }
            if (lane == 0) { red1_s[wc] = s1; red2_s[wc] = s2; }
            __syncthreads();
            if (tid == 0) {
                float t1 = 0.f, t2 = 0.f;
#pragma unroll
                for (int i = 0; i < 32; i++) { t1 += red1_s[i]; t2 += red2_s[i]; }
                float mean = t1 * (1.0f / E);
                float var  = t2 * (1.0f / E) - mean * mean;
                stats[0] = mean;
                stats[1] = rsqrtf(fmaxf(var, 0.f) + 1e-5f);
            }
            __syncthreads();
            float nv = (val - stats[0]) * stats[1];
            h_s[tid] = nv * ln1_g[blk * E + tid] + ln1_b[blk * E + tid];
            __syncthreads();
        }

        // ---- m = cos(h[:4]) * cos(phi_f[blk]);  r = relu(W1[blk] @ m) (redundant) ----
        if (tid < NWF) m_s[tid] = cosf(h_s[tid]) * cosf(phi_f[blk * NWF + tid]);
        __syncthreads();
        {
            const float4* w1 = (const float4*)(W1 + (size_t)blk * FF * NWF);
            float m0 = m_s[0], m1 = m_s[1], m2 = m_s[2], m3 = m_s[3];
#pragma unroll
            for (int j = 0; j < FF / TPB; j++) {
                int ff = tid + j * TPB;
                float4 w = w1[ff];
                float t = w.x * m0 + w.y * m1 + w.z * m2 + w.w * m3;
                r_s[ff] = fmaxf(t, 0.f);
            }
        }
        __syncthreads();

        // ---- f[e] = dot(W2[blk][e,:], r) : warp per output, grid-striped ----
        {
            const float4* rr = (const float4*)r_s;
            for (int e = wc * nb + b; e < E; e += wstride) {
                const float4* row = (const float4*)(W2 + (size_t)blk * E * FF + (size_t)e * FF);
                float acc = warp_dot<FF / 4>(row, rr, lane);
                if (lane == 0) g_f[e] = acc;
            }
        }
        grid_sync();

        // ---- h = LN2(h + f)  (redundant) ----
        {
            float val = h_s[tid] + __ldcg(&g_f[tid]);
            float s1 = val, s2 = val * val;
#pragma unroll
            for (int o = 16; o; o >>= 1) {
                s1 += __shfl_xor_sync(0xffffffffu, s1, o);
                s2 += __shfl_xor_sync(0xffffffffu, s2, o);
            }
            if (lane == 0) { red1_s[wc] = s1; red2_s[wc] = s2; }
            __syncthreads();
            if (tid == 0) {
                float t1 = 0.f, t2 = 0.f;
#pragma unroll
                for (int i = 0; i < 32; i++) { t1 += red1_s[i]; t2 += red2_s[i]; }
                float mean = t1 * (1.0f / E);
                float var  = t2 * (1.0f / E) - mean * mean;
                stats[0] = mean;
                stats[1] = rsqrtf(fmaxf(var, 0.f) + 1e-5f);
            }
            __syncthreads();
            float nv = (val - stats[0]) * stats[1];
            h_s[tid] = nv * ln2_g[blk * E + tid] + ln2_b[blk * E + tid];
            __syncthreads();
        }
    }

    // ---- classifier row: row[c] = dot(Wc[c,:], h) + bc[c] ----
    {
        const float4* hh = (const float4*)h_s;
        for (int c = wc * nb + b; c < CC; c += wstride) {
            const float4* row = (const float4*)(Wc + (size_t)c * E);
            float acc = warp_dot<E / 4>(row, hh, lane);
            if (lane == 0) g_row[c] = acc + bc[c];
        }
    }
    grid_sync();

    // ---- broadcast row to all B=4096 output rows (16.4 MB, float4 stores) ----
    if (tid < CC) r_s[tid] = __ldcg(&g_row[tid]);
    __syncthreads();
    {
        float4* out4 = (float4*)out;
        const float4* row4 = (const float4*)r_s;
        const int total4 = (BB * CC) / 4;          // 1,024,000 ; CC%4==0 so rows are float4-aligned
        for (int idx = b * TPB + tid; idx < total4; idx += nb * TPB) {
            out4[idx] = row4[idx % (CC / 4)];
        }
    }
}

extern "C" void kernel_launch(void* const* d_in, const int* in_sizes, int n_in,
                              void* d_out, int out_size) {
    // metadata order: 0:x 1:Wq 2:Wk 3:Wv 4:Wo 5:phi_q 6:W1 7:W2 8:phi_f
    //                 9:ln1_g 10:ln1_b 11:ln2_g 12:ln2_b 13:Wc 14:bc
    const float* Wv    = (const float*)d_in[3];
    const float* Wo    = (const float*)d_in[4];
    const float* phi_q = (const float*)d_in[5];
    const float* W1    = (const float*)d_in[6];
    const float* W2    = (const float*)d_in[7];
    const float* phi_f = (const float*)d_in[8];
    const float* ln1_g = (const float*)d_in[9];
    const float* ln1_b = (const float*)d_in[10];
    const float* ln2_g = (const float*)d_in[11];
    const float* ln2_b = (const float*)d_in[12];
    const float* Wc    = (const float*)d_in[13];
    const float* bc    = (const float*)d_in[14];

    int dev = 0, sms = 0;
    cudaGetDevice(&dev);
    cudaDeviceGetAttribute(&sms, cudaDevAttrMultiProcessorCount, dev);
    if (sms <= 0) sms = 148;

    // Deadlock safety: the software grid barrier requires every CTA to be
    // resident. Clamp the grid to the occupancy the compiled kernel actually
    // achieves (should be 1 CTA/SM given __launch_bounds__(1024,1)).
    int blocksPerSM = 0;
    cudaOccupancyMaxActiveBlocksPerMultiprocessor(&blocksPerSM, hkt_kernel, TPB, 0);
    int grid = sms;
    if (blocksPerSM < 1) grid = 1;                 // degenerate but terminates
    else if (grid > sms * blocksPerSM) grid = sms * blocksPerSM;

    hkt_kernel<<<grid, TPB>>>(Wv, Wo, phi_q, W1, W2, phi_f,
                              ln1_g, ln1_b, ln2_g, ln2_b, Wc, bc,
                              (float*)d_out);
}